// round 13
// baseline (speedup 1.0000x reference)
#include <cuda_runtime.h>
#include <math.h>

#define NMAX 50000
#define EMAX 800000
#define DS   127
#define NPAD 128
#define EPSF 1e-7f
#define TM   64
#define RPT  8

// Scratch (allocation-free rule: __device__ globals)
__device__ float g_h[(size_t)NMAX * NPAD];
__device__ float g_z[(size_t)NMAX * NPAD];
__device__ float g_Wp[2][NPAD * NPAD];
__device__ int   g_deg[NMAX];          // zeroed by scan each launch (BSS-zero on first)
__device__ int   g_off[NMAX + 1];
__device__ int   g_rank[EMAX];
__device__ int   g_esrc[EMAX];
__device__ float g_ewt[EMAX];

__device__ __forceinline__ float warp_sum(float v) {
#pragma unroll
    for (int o = 16; o > 0; o >>= 1) v += __shfl_xor_sync(0xffffffffu, v, o);
    return v;
}

// scale s.t. logmap0(expmap0(v)) = scale * v, given nv = ||v|| (faithful to ref clamps)
__device__ __forceinline__ float roundtrip_scale(float nv) {
    float n = fmaxf(nv, EPSF);
    float factor = sinhf(n) / n;               // s = factor * v
    float ns = fmaxf(factor * nv, EPSF);       // ||s|| clamped
    float t = coshf(n);
    float d = acoshf(fmaxf(t, 1.0f + EPSF));
    return d * factor / ns;
}

// ==== prep mega-kernel: init rows + repack W1/W2 + hist(+rank) — all concurrent ====
__global__ void prep_kernel(const float* __restrict__ x,
                            const float* __restrict__ W1,
                            const float* __restrict__ W2,
                            const int* __restrict__ dst,
                            int N, int E, int initBlocks, int repackBlocks) {
    int bid = blockIdx.x;
    int tid = threadIdx.x;

    if (bid < initBlocks) {
        // init: h = logmap0(expmap0(x)), one warp per row
        int w = (bid * 256 + tid) >> 5;
        int lane = tid & 31;
        if (w >= N) return;
        const float* xr = x + (size_t)w * DS;
        float v[4];
        float ss = 0.f;
#pragma unroll
        for (int c = 0; c < 4; c++) {
            int j = lane * 4 + c;
            float t = (j < DS) ? xr[j] : 0.f;
            v[c] = t;
            ss += t * t;
        }
        ss = warp_sum(ss);
        float sc = roundtrip_scale(sqrtf(ss));
        float4 o = make_float4(sc * v[0], sc * v[1], sc * v[2], sc * v[3]);
        ((float4*)(g_h + (size_t)w * NPAD))[lane] = o;
        return;
    }
    bid -= initBlocks;

    if (bid < repackBlocks) {
        // repack W into 128x128 zero-padded
        int which = bid >> 6;                 // 64 blocks each
        int i = (bid & 63) * 256 + tid;
        if (i < NPAD * NPAD) {
            int k = i >> 7, j = i & (NPAD - 1);
            const float* W = which ? W2 : W1;
            g_Wp[which][i] = (k < DS && j < DS) ? W[k * DS + j] : 0.f;
        }
        return;
    }
    bid -= repackBlocks;

    // histogram + rank capture (no second atomic pass needed)
    int i = bid * 256 + tid;
    if (i < E) {
        int d = dst[i];
        g_rank[i] = atomicAdd(&g_deg[d], 1);
    }
}

// exclusive scan of g_deg -> g_off by one 256-thread block; resets g_deg to 0
__device__ void scan_body(int N) {
    __shared__ int part[256];
    int t = threadIdx.x;
    int chunk = (N + 255) >> 8;
    int lo = t * chunk;
    int hi = min(lo + chunk, N);
    int s = 0;
    for (int i = lo; i < hi; i++) s += g_deg[i];
    part[t] = s;
    __syncthreads();
    for (int off = 1; off < 256; off <<= 1) {
        int tmp = (t >= off) ? part[t - off] : 0;
        __syncthreads();
        part[t] += tmp;
        __syncthreads();
    }
    int run = part[t] - s;  // exclusive prefix
    for (int i = lo; i < hi; i++) {
        g_off[i] = run;
        run += g_deg[i];
        g_deg[i] = 0;       // reset for next launch (determinism across replays)
    }
    if (t == 255) g_off[N] = run;
}

// z = h @ W + b  (scalar FFMA — measured-good). Blocks >= nblk run the CSR scan.
__global__ void gemm_kernel(const float* __restrict__ b, int N, int which, unsigned nblk) {
    __shared__ float hs[TM][NPAD];   // 32 KB
    if (blockIdx.x >= nblk) { scan_body(N); return; }

    const float* Wp = g_Wp[which];
    int tx = threadIdx.x & 31;
    int ty = threadIdx.x >> 5;
    int row0 = blockIdx.x * TM;

    for (int idx = threadIdx.x; idx < TM * (NPAD / 4); idx += 256) {
        int r = idx >> 5;
        int c = idx & 31;
        int gr = row0 + r;
        float4 t = (gr < N) ? ((const float4*)(g_h + (size_t)gr * NPAD))[c]
                            : make_float4(0.f, 0.f, 0.f, 0.f);
        ((float4*)&hs[r][0])[c] = t;
    }
    __syncthreads();

    float4 acc[RPT];
#pragma unroll
    for (int r = 0; r < RPT; r++) acc[r] = make_float4(0.f, 0.f, 0.f, 0.f);

#pragma unroll 4
    for (int k = 0; k < DS; k++) {
        float4 wv = *((const float4*)(Wp + (size_t)k * NPAD + tx * 4));
#pragma unroll
        for (int r = 0; r < RPT; r++) {
            float hv = hs[ty * RPT + r][k];
            acc[r].x += hv * wv.x;
            acc[r].y += hv * wv.y;
            acc[r].z += hv * wv.z;
            acc[r].w += hv * wv.w;
        }
    }

    int j0 = tx * 4;
    float b0 = (j0 + 0 < DS) ? b[j0 + 0] : 0.f;
    float b1 = (j0 + 1 < DS) ? b[j0 + 1] : 0.f;
    float b2 = (j0 + 2 < DS) ? b[j0 + 2] : 0.f;
    float b3 = (j0 + 3 < DS) ? b[j0 + 3] : 0.f;
#pragma unroll
    for (int r = 0; r < RPT; r++) {
        int gr = row0 + ty * RPT + r;
        if (gr < N) {
            float4 o;
            o.x = acc[r].x + b0;
            o.y = acc[r].y + b1;
            o.z = acc[r].z + b2;
            o.w = (j0 + 3 < DS) ? (acc[r].w + b3) : 0.f;   // pad col stays 0
            ((float4*)(g_z + (size_t)gr * NPAD))[tx] = o;
        }
    }
}

// scatter with precomputed ranks — no atomics
__global__ void scatter_kernel(const int* __restrict__ src, const int* __restrict__ dst,
                               const float* __restrict__ w, int E) {
    int i = blockIdx.x * blockDim.x + threadIdx.x;
    if (i >= E) return;
    int d = dst[i];
    int p = g_off[d] + g_rank[i];
    g_esrc[p] = src[i];
    g_ewt[p]  = w[i];
}

// Fused: agg = sum CSR row;  h = roundtrip(relu(agg) + h).
// If out != nullptr (final layer), write expmap0(h_new) directly instead of h.
__global__ void agg_kernel(int N, float* __restrict__ out) {
    int row = (blockIdx.x * blockDim.x + threadIdx.x) >> 5;
    int lane = threadIdx.x & 31;
    if (row >= N) return;
    int lo = g_off[row];
    int hi = g_off[row + 1];

    float4 acc = make_float4(0.f, 0.f, 0.f, 0.f);
    for (int base = lo; base < hi; base += 32) {
        int n = min(32, hi - base);
        int s = 0; float wt = 0.f;
        if (lane < n) {
            s  = __ldg(g_esrc + base + lane);
            wt = __ldg(g_ewt + base + lane);
        }
#pragma unroll 8
        for (int j = 0; j < n; j++) {
            int   sj = __shfl_sync(0xffffffffu, s, j);
            float wj = __shfl_sync(0xffffffffu, wt, j);
            float4 v = __ldcg((const float4*)(g_z + (size_t)sj * NPAD) + lane);
            acc.x += wj * v.x;
            acc.y += wj * v.y;
            acc.z += wj * v.z;
            acc.w += wj * v.w;
        }
    }

    float4 h = ((const float4*)(g_h + (size_t)row * NPAD))[lane];
    float4 v;
    v.x = fmaxf(acc.x, 0.f) + h.x;
    v.y = fmaxf(acc.y, 0.f) + h.y;
    v.z = fmaxf(acc.z, 0.f) + h.z;
    v.w = fmaxf(acc.w, 0.f) + h.w;   // pad col: 0 + 0
    float ss = v.x * v.x + v.y * v.y + v.z * v.z + v.w * v.w;
    ss = warp_sum(ss);
    float nv = sqrtf(ss);
    float sc = roundtrip_scale(nv);

    if (out == nullptr) {
        float4 o = make_float4(sc * v.x, sc * v.y, sc * v.z, sc * v.w);
        ((float4*)(g_h + (size_t)row * NPAD))[lane] = o;
    } else {
        // final: emit expmap0(h_new) where h_new = sc*v, ||h_new|| = sc*nv
        float nh = sc * nv;
        float n = fmaxf(nh, EPSF);
        float t = coshf(n);
        float factor = sinhf(n) / n * sc;      // applied directly to v
        float* orow = out + (size_t)row * NPAD;
        if (lane == 0) orow[0] = t;
        int j = lane * 4;
        orow[j + 1] = factor * v.x;
        orow[j + 2] = factor * v.y;
        orow[j + 3] = factor * v.z;
        if (j + 4 < NPAD) orow[j + 4] = factor * v.w;   // lane 31's 4th is pad
    }
}

extern "C" void kernel_launch(void* const* d_in, const int* in_sizes, int n_in,
                              void* d_out, int out_size) {
    const float* x  = (const float*)d_in[0];
    const float* W1 = (const float*)d_in[1];
    const float* b1 = (const float*)d_in[2];
    const float* W2 = (const float*)d_in[3];
    const float* b2 = (const float*)d_in[4];
    const int*   es = (const int*)d_in[5];
    const int*   ed = (const int*)d_in[6];
    const float* ew = (const float*)d_in[7];

    int N = in_sizes[0] / DS;
    if (N > NMAX) N = NMAX;
    int E = in_sizes[5];
    if (E > EMAX) E = EMAX;

    int initBlocks   = (N * 32 + 255) / 256;
    int repackBlocks = 2 * (NPAD * NPAD / 256);   // 128
    int histBlocks   = (E + 255) / 256;
    int prepBlocks   = initBlocks + repackBlocks + histBlocks;
    int gemmBlocks   = (N + TM - 1) / TM;
    int rowWarpBlocks = initBlocks;

    prep_kernel<<<prepBlocks, 256>>>(x, W1, W2, ed, N, E, initBlocks, repackBlocks);

    // layer 0 gemm + CSR scan (extra block)
    gemm_kernel<<<gemmBlocks + 1, 256>>>(b1, N, 0, (unsigned)gemmBlocks);
    scatter_kernel<<<(E + 255) / 256, 256>>>(es, ed, ew, E);
    agg_kernel<<<rowWarpBlocks, 256>>>(N, nullptr);

    // layer 1
    gemm_kernel<<<gemmBlocks, 256>>>(b2, N, 1, (unsigned)gemmBlocks);
    agg_kernel<<<rowWarpBlocks, 256>>>(N, (float*)d_out);
}

// round 14
// speedup vs baseline: 1.3855x; 1.3855x over previous
#include <cuda_runtime.h>
#include <cuda_fp16.h>
#include <math.h>

#define NMAX 50000
#define EMAX 800000
#define DS   127
#define NPAD 128
#define EPSF 1e-7f
#define TM   64
#define RPT  8

// Scratch (allocation-free rule: __device__ globals)
__device__ float g_h[(size_t)NMAX * NPAD];
__device__ uint2 g_z[(size_t)NMAX * 32];     // fp16x2 packed: 32 uint2 = 128 halfs/row
__device__ float g_Wp[2][NPAD * NPAD];
__device__ int   g_deg[NMAX];
__device__ int   g_cur[NMAX];
__device__ int   g_off[NMAX + 1];
__device__ int   g_esrc[EMAX];
__device__ float g_ewt[EMAX];

__device__ __forceinline__ float warp_sum(float v) {
#pragma unroll
    for (int o = 16; o > 0; o >>= 1) v += __shfl_xor_sync(0xffffffffu, v, o);
    return v;
}

// scale s.t. logmap0(expmap0(v)) = scale * v, given nv = ||v|| (faithful to ref clamps)
__device__ __forceinline__ float roundtrip_scale(float nv) {
    float n = fmaxf(nv, EPSF);
    float factor = sinhf(n) / n;               // s = factor * v
    float ns = fmaxf(factor * nv, EPSF);       // ||s|| clamped
    float t = coshf(n);
    float d = acoshf(fmaxf(t, 1.0f + EPSF));
    return d * factor / ns;
}

// h = logmap0(expmap0(x)); also zero CSR counters (fresh per launch)
__global__ void init_kernel(const float* __restrict__ x, int N) {
    int w = (blockIdx.x * blockDim.x + threadIdx.x) >> 5;
    int lane = threadIdx.x & 31;
    if (w >= N) return;
    const float* xr = x + (size_t)w * DS;
    float v[4];
    float ss = 0.f;
#pragma unroll
    for (int c = 0; c < 4; c++) {
        int j = lane * 4 + c;
        float t = (j < DS) ? xr[j] : 0.f;
        v[c] = t;
        ss += t * t;
    }
    ss = warp_sum(ss);
    float sc = roundtrip_scale(sqrtf(ss));
    float4 o = make_float4(sc * v[0], sc * v[1], sc * v[2], sc * v[3]); // pad col -> 0
    ((float4*)(g_h + (size_t)w * NPAD))[lane] = o;
    if (lane == 0) { g_deg[w] = 0; g_cur[w] = 0; }
}

// pack both W (127x127) into 128x128 zero-padded buffers (one launch, 128 blocks)
__global__ void repack_kernel(const float* __restrict__ W1, const float* __restrict__ W2) {
    int which = blockIdx.x >> 6;                  // 64 blocks each
    int i = (blockIdx.x & 63) * 256 + threadIdx.x;
    if (i >= NPAD * NPAD) return;
    int k = i >> 7, j = i & (NPAD - 1);
    const float* W = which ? W2 : W1;
    g_Wp[which][i] = (k < DS && j < DS) ? W[k * DS + j] : 0.f;
}

// ---- CSR build (once per launch, reused by both layers) ----
__global__ void hist_kernel(const int* __restrict__ dst, int E) {
    int i = blockIdx.x * blockDim.x + threadIdx.x;
    if (i < E) atomicAdd(&g_deg[dst[i]], 1);      // no return -> RED
}

// single-block exclusive scan of g_deg -> g_off (1024 threads, as measured-good)
__global__ void scan_kernel(int N) {
    __shared__ int part[1024];
    int t = threadIdx.x;
    int chunk = (N + 1023) >> 10;
    int lo = t * chunk;
    int hi = min(lo + chunk, N);
    int s = 0;
    for (int i = lo; i < hi; i++) s += g_deg[i];
    part[t] = s;
    __syncthreads();
    for (int off = 1; off < 1024; off <<= 1) {
        int tmp = (t >= off) ? part[t - off] : 0;
        __syncthreads();
        part[t] += tmp;
        __syncthreads();
    }
    int run = part[t] - s;  // exclusive prefix
    for (int i = lo; i < hi; i++) {
        g_off[i] = run;
        run += g_deg[i];
    }
    if (t == 1023) g_off[N] = run;
}

__global__ void scatter_kernel(const int* __restrict__ src, const int* __restrict__ dst,
                               const float* __restrict__ w, int E) {
    int i = blockIdx.x * blockDim.x + threadIdx.x;
    if (i >= E) return;
    int d = dst[i];
    int p = g_off[d] + atomicAdd(&g_cur[d], 1);
    g_esrc[p] = src[i];
    g_ewt[p]  = w[i];
}

// z = h @ W + b  (scalar FFMA — at roofline). Output packed fp16.
__global__ void gemm_kernel(const float* __restrict__ b, int N, int which) {
    __shared__ float hs[TM][NPAD];   // 32 KB
    const float* Wp = g_Wp[which];
    int tx = threadIdx.x & 31;
    int ty = threadIdx.x >> 5;
    int row0 = blockIdx.x * TM;

    for (int idx = threadIdx.x; idx < TM * (NPAD / 4); idx += 256) {
        int r = idx >> 5;
        int c = idx & 31;
        int gr = row0 + r;
        float4 t = (gr < N) ? ((const float4*)(g_h + (size_t)gr * NPAD))[c]
                            : make_float4(0.f, 0.f, 0.f, 0.f);
        ((float4*)&hs[r][0])[c] = t;
    }
    __syncthreads();

    float4 acc[RPT];
#pragma unroll
    for (int r = 0; r < RPT; r++) acc[r] = make_float4(0.f, 0.f, 0.f, 0.f);

#pragma unroll 4
    for (int k = 0; k < DS; k++) {
        float4 wv = *((const float4*)(Wp + (size_t)k * NPAD + tx * 4));
#pragma unroll
        for (int r = 0; r < RPT; r++) {
            float hv = hs[ty * RPT + r][k];
            acc[r].x += hv * wv.x;
            acc[r].y += hv * wv.y;
            acc[r].z += hv * wv.z;
            acc[r].w += hv * wv.w;
        }
    }

    int j0 = tx * 4;
    float b0 = (j0 + 0 < DS) ? b[j0 + 0] : 0.f;
    float b1 = (j0 + 1 < DS) ? b[j0 + 1] : 0.f;
    float b2 = (j0 + 2 < DS) ? b[j0 + 2] : 0.f;
    float b3 = (j0 + 3 < DS) ? b[j0 + 3] : 0.f;
#pragma unroll
    for (int r = 0; r < RPT; r++) {
        int gr = row0 + ty * RPT + r;
        if (gr < N) {
            float ox = acc[r].x + b0;
            float oy = acc[r].y + b1;
            float oz = acc[r].z + b2;
            float ow = (j0 + 3 < DS) ? (acc[r].w + b3) : 0.f;   // pad col stays 0
            __half2 ha = __floats2half2_rn(ox, oy);
            __half2 hb = __floats2half2_rn(oz, ow);
            uint2 pk;
            pk.x = *reinterpret_cast<unsigned*>(&ha);
            pk.y = *reinterpret_cast<unsigned*>(&hb);
            g_z[(size_t)gr * 32 + tx] = pk;
        }
    }
}

// Fused: agg = sum CSR row (fp16 gather, fp32 accumulate); h = roundtrip(relu(agg)+h).
// If out != nullptr (final layer), write expmap0(h_new) directly instead of h.
__global__ void agg_kernel(int N, float* __restrict__ out) {
    int row = (blockIdx.x * blockDim.x + threadIdx.x) >> 5;
    int lane = threadIdx.x & 31;
    if (row >= N) return;
    int lo = g_off[row];
    int hi = g_off[row + 1];

    float4 acc = make_float4(0.f, 0.f, 0.f, 0.f);
    for (int base = lo; base < hi; base += 32) {
        int n = min(32, hi - base);
        int s = 0; float wt = 0.f;
        if (lane < n) {
            s  = __ldg(g_esrc + base + lane);
            wt = __ldg(g_ewt + base + lane);
        }
#pragma unroll 8
        for (int j = 0; j < n; j++) {
            int   sj = __shfl_sync(0xffffffffu, s, j);
            float wj = __shfl_sync(0xffffffffu, wt, j);
            uint2 raw = __ldcg(&g_z[(size_t)sj * 32 + lane]);
            __half2 p0 = *reinterpret_cast<__half2*>(&raw.x);
            __half2 p1 = *reinterpret_cast<__half2*>(&raw.y);
            float2 f0 = __half22float2(p0);
            float2 f1 = __half22float2(p1);
            acc.x += wj * f0.x;
            acc.y += wj * f0.y;
            acc.z += wj * f1.x;
            acc.w += wj * f1.y;
        }
    }

    float4 h = ((const float4*)(g_h + (size_t)row * NPAD))[lane];
    float4 v;
    v.x = fmaxf(acc.x, 0.f) + h.x;
    v.y = fmaxf(acc.y, 0.f) + h.y;
    v.z = fmaxf(acc.z, 0.f) + h.z;
    v.w = fmaxf(acc.w, 0.f) + h.w;   // pad col: 0 + 0
    float ss = v.x * v.x + v.y * v.y + v.z * v.z + v.w * v.w;
    ss = warp_sum(ss);
    float nv = sqrtf(ss);
    float sc = roundtrip_scale(nv);

    if (out == nullptr) {
        float4 o = make_float4(sc * v.x, sc * v.y, sc * v.z, sc * v.w);
        ((float4*)(g_h + (size_t)row * NPAD))[lane] = o;
    } else {
        // final: emit expmap0(h_new) where h_new = sc*v, ||h_new|| = sc*nv
        float nh = sc * nv;
        float n = fmaxf(nh, EPSF);
        float t = coshf(n);
        float factor = sinhf(n) / n * sc;      // applied directly to v
        float* orow = out + (size_t)row * NPAD;
        if (lane == 0) orow[0] = t;
        int j = lane * 4;
        orow[j + 1] = factor * v.x;
        orow[j + 2] = factor * v.y;
        orow[j + 3] = factor * v.z;
        if (j + 4 < NPAD) orow[j + 4] = factor * v.w;   // lane 31's 4th is pad
    }
}

extern "C" void kernel_launch(void* const* d_in, const int* in_sizes, int n_in,
                              void* d_out, int out_size) {
    const float* x  = (const float*)d_in[0];
    const float* W1 = (const float*)d_in[1];
    const float* b1 = (const float*)d_in[2];
    const float* W2 = (const float*)d_in[3];
    const float* b2 = (const float*)d_in[4];
    const int*   es = (const int*)d_in[5];
    const int*   ed = (const int*)d_in[6];
    const float* ew = (const float*)d_in[7];

    int N = in_sizes[0] / DS;
    if (N > NMAX) N = NMAX;
    int E = in_sizes[5];
    if (E > EMAX) E = EMAX;

    int rowWarpBlocks = (N * 32 + 255) / 256;
    int eBlocks = (E + 255) / 256;
    int gemmBlocks = (N + TM - 1) / TM;

    init_kernel<<<rowWarpBlocks, 256>>>(x, N);
    repack_kernel<<<128, 256>>>(W1, W2);

    // CSR build (reused by both layers)
    hist_kernel<<<eBlocks, 256>>>(ed, E);
    scan_kernel<<<1, 1024>>>(N);
    scatter_kernel<<<eBlocks, 256>>>(es, ed, ew, E);

    // layer 0
    gemm_kernel<<<gemmBlocks, 256>>>(b1, N, 0);
    agg_kernel<<<rowWarpBlocks, 256>>>(N, nullptr);
    // layer 1
    gemm_kernel<<<gemmBlocks, 256>>>(b2, N, 1);
    agg_kernel<<<rowWarpBlocks, 256>>>(N, (float*)d_out);
}